// round 2
// baseline (speedup 1.0000x reference)
#include <cuda_runtime.h>
#include <float.h>

#define HWC   2304      // H*W = 48*48
#define BATCH 8
#define QCH   64        // q-chunk size in global kernel
#define NQCH  (HWC / QCH)   // 36

// Scratch: per-(batch, channel) max of "dropped" value d = max(scale*rowmin, 0)
__device__ float g_D[BATCH * 2];

// Float atomic max using signed-int max / unsigned-int min trick.
// Valid because IEEE-754 floats order like sign-magnitude ints.
__device__ __forceinline__ void atomicMaxF(float* addr, float val) {
    if (val >= 0.0f) atomicMax((int*)addr, __float_as_int(val));
    else             atomicMin((unsigned int*)addr, __float_as_uint(val));
}

__global__ void init_kernel(float* __restrict__ out) {
    int i = blockIdx.x * blockDim.x + threadIdx.x;
    if (i < BATCH * 4 * HWC) out[i] = -FLT_MAX;
    if (i < BATCH * 2)       g_D[i] = -FLT_MAX;
}

// Global branch: out[b, ch, p] = max_q sim[b,q,p] * seg[b,ch,q]  (ch = 0,1)
// grid: x = p-tile (9), y = q-chunk (36), z = batch (8). block = 256.
__global__ void global_kernel(const float* __restrict__ sim,
                              const float* __restrict__ seg,
                              float* __restrict__ out) {
    const int b  = blockIdx.z;
    const int p  = blockIdx.x * 256 + threadIdx.x;      // 0..2303
    const int q0 = blockIdx.y * QCH;

    __shared__ float w0s[QCH], w1s[QCH];
    if (threadIdx.x < QCH)
        w0s[threadIdx.x] = seg[(b * 2 + 0) * HWC + q0 + threadIdx.x];
    else if (threadIdx.x < 2 * QCH)
        w1s[threadIdx.x - QCH] = seg[(b * 2 + 1) * HWC + q0 + (threadIdx.x - QCH)];
    __syncthreads();

    const float* base = sim + ((size_t)b * HWC + q0) * HWC + p;
    float a0 = -FLT_MAX, a1 = -FLT_MAX;
#pragma unroll 8
    for (int j = 0; j < QCH; j++) {
        float v = base[(size_t)j * HWC];
        a0 = fmaxf(a0, v * w0s[j]);
        a1 = fmaxf(a1, v * w1s[j]);
    }
    atomicMaxF(&out[(size_t)(b * 4 + 0) * HWC + p], a0);
    atomicMaxF(&out[(size_t)(b * 4 + 1) * HWC + p], a1);
}

// Local branch stats: one block per (b, q) row of prev_sim.
// Computes row min and top-4 (values + column indices) of the RAW row.
// Scale is positive, so scaled ordering == raw ordering.
// Emits: atomicMax of d into g_D, and 4 sparse atomicMax into out channels 2,3.
__global__ void local_kernel(const float* __restrict__ sim,
                             const float* __restrict__ seg,
                             float* __restrict__ out) {
    const int row = blockIdx.x;                 // b*HWC + q
    const int b   = row / HWC;
    const int q   = row - b * HWC;
    const int tid = threadIdx.x;                // 256 threads
    const float* r = sim + (size_t)row * HWC;

    // per-thread top-4 (descending) and min over its 9 strided elements
    float v0 = -FLT_MAX, v1 = -FLT_MAX, v2 = -FLT_MAX, v3 = -FLT_MAX;
    int   i0 = -1, i1 = -1, i2 = -1, i3 = -1;
    float mn = FLT_MAX;
#pragma unroll
    for (int j = 0; j < HWC / 256; j++) {
        int p = tid + j * 256;
        float x = r[p];
        mn = fminf(mn, x);
        if (x > v3) {
            if (x > v0)      { v3=v2;i3=i2; v2=v1;i2=i1; v1=v0;i1=i0; v0=x;i0=p; }
            else if (x > v1) { v3=v2;i3=i2; v2=v1;i2=i1; v1=x;i1=p; }
            else if (x > v2) { v3=v2;i3=i2; v2=x;i2=p; }
            else             { v3=x;i3=p; }
        }
    }

    // warp min
#pragma unroll
    for (int o = 16; o; o >>= 1) mn = fminf(mn, __shfl_xor_sync(0xffffffffu, mn, o));

    // warp top-4: 4 argmax rounds over each lane's list head (idx breaks ties;
    // indices are unique per lane so exactly one lane pops per round)
    float wv[4]; int wix[4];
#pragma unroll
    for (int rr = 0; rr < 4; rr++) {
        float bv = v0; int bi = i0;
#pragma unroll
        for (int o = 16; o; o >>= 1) {
            float ov = __shfl_xor_sync(0xffffffffu, bv, o);
            int   oi = __shfl_xor_sync(0xffffffffu, bi, o);
            if (ov > bv || (ov == bv && oi > bi)) { bv = ov; bi = oi; }
        }
        wv[rr] = bv; wix[rr] = bi;
        if (v0 == bv && i0 == bi) { v0=v1;i0=i1; v1=v2;i1=i2; v2=v3;i2=i3; v3=-FLT_MAX;i3=-1; }
    }

    // cross-warp merge: 8 warps x 4 entries = 32 entries, merged by warp 0
    __shared__ float sv[32];
    __shared__ int   si[32];
    __shared__ float smn[8];
    const int wid = tid >> 5, lane = tid & 31;
    if (lane == 0) smn[wid] = mn;
    if (lane < 4) { sv[wid * 4 + lane] = wv[lane]; si[wid * 4 + lane] = wix[lane]; }
    __syncthreads();

    if (wid == 0) {
        float m2 = (lane < 8) ? smn[lane] : FLT_MAX;
#pragma unroll
        for (int o = 16; o; o >>= 1) m2 = fminf(m2, __shfl_xor_sync(0xffffffffu, m2, o));

        float cv = sv[lane]; int ci = si[lane];
        float fv[4]; int fi[4];
#pragma unroll
        for (int rr = 0; rr < 4; rr++) {
            float bv = cv; int bi = ci;
#pragma unroll
            for (int o = 16; o; o >>= 1) {
                float ov = __shfl_xor_sync(0xffffffffu, bv, o);
                int   oi = __shfl_xor_sync(0xffffffffu, bi, o);
                if (ov > bv || (ov == bv && oi > bi)) { bv = ov; bi = oi; }
            }
            fv[rr] = bv; fi[rr] = bi;
            if (cv == bv && ci == bi) { cv = -FLT_MAX; ci = -1; }
        }

        if (lane == 0) {
#pragma unroll
            for (int ch = 0; ch < 2; ch++) {
                float scale = seg[(b * 2 + ch) * HWC + q];
                float d = fmaxf(scale * m2, 0.0f);
                atomicMaxF(&g_D[b * 2 + ch], d);
                float* o = out + (size_t)(b * 4 + 2 + ch) * HWC;
#pragma unroll
                for (int k = 0; k < 4; k++) atomicMaxF(&o[fi[k]], scale * fv[k]);
            }
        }
    }
}

// Merge the broadcast "dropped" value D into local-branch channels (2,3).
__global__ void finalize_kernel(float* __restrict__ out) {
    int i = blockIdx.x * blockDim.x + threadIdx.x;   // over BATCH*2*HWC
    if (i >= BATCH * 2 * HWC) return;
    int b   = i / (2 * HWC);
    int rem = i - b * 2 * HWC;
    int ch  = rem / HWC;
    int p   = rem - ch * HWC;
    float D = g_D[b * 2 + ch];
    float* o = &out[(size_t)(b * 4 + 2 + ch) * HWC + p];
    *o = fmaxf(*o, D);
}

extern "C" void kernel_launch(void* const* d_in, const int* in_sizes, int n_in,
                              void* d_out, int out_size) {
    const float* init_sim = (const float*)d_in[0];
    const float* prev_sim = (const float*)d_in[1];
    const float* init_seg = (const float*)d_in[2];
    const float* prev_seg = (const float*)d_in[3];
    float* out = (float*)d_out;

    init_kernel<<<(BATCH * 4 * HWC + 255) / 256, 256>>>(out);

    dim3 g(HWC / 256, NQCH, BATCH);   // (9, 36, 8)
    global_kernel<<<g, 256>>>(init_sim, init_seg, out);

    local_kernel<<<BATCH * HWC, 256>>>(prev_sim, prev_seg, out);

    finalize_kernel<<<(BATCH * 2 * HWC + 255) / 256, 256>>>(out);
}

// round 3
// speedup vs baseline: 1.2808x; 1.2808x over previous
#include <cuda_runtime.h>
#include <float.h>

#define HWC   2304      // H*W = 48*48
#define BATCH 8
#define GQCH  32        // q-chunk in global kernel
#define GNQ   (HWC / GQCH)   // 72

// per-(batch, channel) max of "dropped" value d = max(scale*rowmin, 0) >= 0
__device__ float g_D[BATCH * 2];

// Float atomic max via signed-int max / unsigned-int min (IEEE order trick).
__device__ __forceinline__ void atomicMaxF(float* addr, float val) {
    if (val >= 0.0f) atomicMax((int*)addr, __float_as_int(val));
    else             atomicMin((unsigned int*)addr, __float_as_uint(val));
}

__global__ void init_kernel(float* __restrict__ out) {
    int i = blockIdx.x * blockDim.x + threadIdx.x;
    if (i < BATCH * 4 * HWC) out[i] = -FLT_MAX;
    if (i < BATCH * 2)       g_D[i] = 0.0f;   // d >= 0 always
}

// Global branch: out[b,ch,p] = max_q sim[b,q,p] * seg[b,ch,q], ch=0,1.
// grid (3, 72, 8), block 192. Each thread owns 4 consecutive p (float4).
__global__ void __launch_bounds__(192) global_kernel(
        const float* __restrict__ sim,
        const float* __restrict__ seg,
        float* __restrict__ out) {
    const int b  = blockIdx.z;
    const int q0 = blockIdx.y * GQCH;
    const int t  = threadIdx.x;
    const int p4 = blockIdx.x * 192 + t;      // float4 index 0..575

    __shared__ float2 w[GQCH];
    if (t < GQCH)
        w[t] = make_float2(seg[(b * 2 + 0) * HWC + q0 + t],
                           seg[(b * 2 + 1) * HWC + q0 + t]);
    __syncthreads();

    const float4* base = reinterpret_cast<const float4*>(
        sim + ((size_t)b * HWC + q0) * HWC) + p4;

    float4 a0 = make_float4(-FLT_MAX, -FLT_MAX, -FLT_MAX, -FLT_MAX);
    float4 a1 = a0;
#pragma unroll 8
    for (int j = 0; j < GQCH; j++) {
        float4 v  = base[(size_t)j * (HWC / 4)];
        float2 ww = w[j];
        a0.x = fmaxf(a0.x, v.x * ww.x); a0.y = fmaxf(a0.y, v.y * ww.x);
        a0.z = fmaxf(a0.z, v.z * ww.x); a0.w = fmaxf(a0.w, v.w * ww.x);
        a1.x = fmaxf(a1.x, v.x * ww.y); a1.y = fmaxf(a1.y, v.y * ww.y);
        a1.z = fmaxf(a1.z, v.z * ww.y); a1.w = fmaxf(a1.w, v.w * ww.y);
    }
    float* o0 = out + (size_t)(b * 4 + 0) * HWC + 4 * p4;
    float* o1 = out + (size_t)(b * 4 + 1) * HWC + 4 * p4;
    atomicMaxF(o0 + 0, a0.x); atomicMaxF(o0 + 1, a0.y);
    atomicMaxF(o0 + 2, a0.z); atomicMaxF(o0 + 3, a0.w);
    atomicMaxF(o1 + 0, a1.x); atomicMaxF(o1 + 1, a1.y);
    atomicMaxF(o1 + 2, a1.z); atomicMaxF(o1 + 3, a1.w);
}

// Merge two descending sorted 4-lists held across shuffle distance o.
#define MERGE4(o)                                                              \
    {                                                                          \
        float b0 = __shfl_xor_sync(0xffffffffu, v0, o);                        \
        float b1 = __shfl_xor_sync(0xffffffffu, v1, o);                        \
        float b2 = __shfl_xor_sync(0xffffffffu, v2, o);                        \
        float b3 = __shfl_xor_sync(0xffffffffu, v3, o);                        \
        mn = fminf(mn, __shfl_xor_sync(0xffffffffu, mn, o));                   \
        float c0 = fmaxf(v0, b3), c1 = fmaxf(v1, b2);                          \
        float c2 = fmaxf(v2, b1), c3 = fmaxf(v3, b0);                          \
        float tt;                                                              \
        tt = fmaxf(c0, c2); c2 = fminf(c0, c2); c0 = tt;                       \
        tt = fmaxf(c1, c3); c3 = fminf(c1, c3); c1 = tt;                       \
        tt = fmaxf(c0, c1); c1 = fminf(c0, c1); c0 = tt;                       \
        tt = fmaxf(c2, c3); c3 = fminf(c2, c3); c2 = tt;                       \
        v0 = c0; v1 = c1; v2 = c2; v3 = c3;                                    \
    }

// Local branch: one block (192 thr) per row of prev_sim.
// Pass 1: branchless top-4-values lattice + row min, all in registers.
// Merge values-only -> cut (4th largest of raw row; scale>0 preserves order).
// Pass 2 (registers): emit scale*x for every x >= cut (matches ref's >=cut
// keep-set incl. ties); push d = max(scale*min, 0) to g_D.
__global__ void __launch_bounds__(192) local_kernel(
        const float* __restrict__ sim,
        const float* __restrict__ seg,
        float* __restrict__ out) {
    const int row  = blockIdx.x;              // b*HWC + q
    const int b    = row / HWC;
    const int q    = row - b * HWC;
    const int t    = threadIdx.x;             // 0..191
    const int lane = t & 31, wid = t >> 5;    // 6 warps

    __shared__ float s_v[6 * 4];
    __shared__ float s_mn[6];
    __shared__ float s_bcast[4];              // cut, rowmin, sc0, sc1

    if (t < 2) s_bcast[2 + t] = seg[(b * 2 + t) * HWC + q];

    const float4* r4 = reinterpret_cast<const float4*>(sim + (size_t)row * HWC);
    float4 d0 = r4[t], d1 = r4[t + 192], d2 = r4[t + 384];
    float x[12] = { d0.x, d0.y, d0.z, d0.w,
                    d1.x, d1.y, d1.z, d1.w,
                    d2.x, d2.y, d2.z, d2.w };

    float v0 = -FLT_MAX, v1 = -FLT_MAX, v2 = -FLT_MAX, v3 = -FLT_MAX;
    float mn = FLT_MAX;
#pragma unroll
    for (int j = 0; j < 12; j++) {
        float xx = x[j];
        mn = fminf(mn, xx);
        v3 = fminf(v2, fmaxf(v3, xx));    // branchless sorted-4 lattice
        v2 = fminf(v1, fmaxf(v2, xx));
        v1 = fminf(v0, fmaxf(v1, xx));
        v0 = fmaxf(v0, xx);
    }

    // warp-level merge of sorted 4-lists (values only)
    MERGE4(16); MERGE4(8); MERGE4(4); MERGE4(2); MERGE4(1);

    if (lane == 0) {
        s_v[wid * 4 + 0] = v0; s_v[wid * 4 + 1] = v1;
        s_v[wid * 4 + 2] = v2; s_v[wid * 4 + 3] = v3;
        s_mn[wid] = mn;
    }
    __syncthreads();

    if (wid == 0) {
        if (lane < 6) {
            v0 = s_v[lane * 4 + 0]; v1 = s_v[lane * 4 + 1];
            v2 = s_v[lane * 4 + 2]; v3 = s_v[lane * 4 + 3];
            mn = s_mn[lane];
        } else {
            v0 = v1 = v2 = v3 = -FLT_MAX; mn = FLT_MAX;
        }
        MERGE4(4); MERGE4(2); MERGE4(1);
        if (lane == 0) { s_bcast[0] = v3; s_bcast[1] = mn; }
    }
    __syncthreads();

    const float cut = s_bcast[0];
    const float sc0 = s_bcast[2], sc1 = s_bcast[3];
    float* o2 = out + (size_t)(b * 4 + 2) * HWC;
    float* o3 = out + (size_t)(b * 4 + 3) * HWC;
#pragma unroll
    for (int j = 0; j < 12; j++) {
        if (x[j] >= cut) {
            int p = 4 * t + 768 * (j >> 2) + (j & 3);
            atomicMaxF(o2 + p, sc0 * x[j]);
            atomicMaxF(o3 + p, sc1 * x[j]);
        }
    }
    if (t == 0) {
        float mrow = s_bcast[1];
        atomicMaxF(&g_D[b * 2 + 0], fmaxf(sc0 * mrow, 0.0f));
        atomicMaxF(&g_D[b * 2 + 1], fmaxf(sc1 * mrow, 0.0f));
    }
}

// Merge broadcast "dropped" value D into local channels (2,3).
__global__ void finalize_kernel(float* __restrict__ out) {
    int i = blockIdx.x * blockDim.x + threadIdx.x;   // over BATCH*2*HWC
    if (i >= BATCH * 2 * HWC) return;
    int b   = i / (2 * HWC);
    int rem = i - b * 2 * HWC;
    int ch  = rem / HWC;
    int p   = rem - ch * HWC;
    float D = g_D[b * 2 + ch];
    float* o = &out[(size_t)(b * 4 + 2 + ch) * HWC + p];
    *o = fmaxf(*o, D);
}

extern "C" void kernel_launch(void* const* d_in, const int* in_sizes, int n_in,
                              void* d_out, int out_size) {
    const float* init_sim = (const float*)d_in[0];
    const float* prev_sim = (const float*)d_in[1];
    const float* init_seg = (const float*)d_in[2];
    const float* prev_seg = (const float*)d_in[3];
    float* out = (float*)d_out;

    init_kernel<<<(BATCH * 4 * HWC + 255) / 256, 256>>>(out);

    dim3 g(3, GNQ, BATCH);                     // (3, 72, 8) = 1728 blocks
    global_kernel<<<g, 192>>>(init_sim, init_seg, out);

    local_kernel<<<BATCH * HWC, 192>>>(prev_sim, prev_seg, out);

    finalize_kernel<<<(BATCH * 2 * HWC + 255) / 256, 256>>>(out);
}

// round 4
// speedup vs baseline: 1.3720x; 1.0712x over previous
#include <cuda_runtime.h>
#include <float.h>

#define HWC   2304      // H*W = 48*48
#define BATCH 8
#define GQCH  64        // q-chunk in global kernel
#define LROWS 4         // rows per local block (one warp each)
#define LCAP  128       // candidate-list capacity per row

// per-(batch, channel) max of "dropped" value d = max(scale*rowmin, 0) >= 0
__device__ float g_D[BATCH * 2];

// Float atomic max via signed-int max / unsigned-int min (IEEE order trick).
__device__ __forceinline__ void atomicMaxF(float* addr, float val) {
    if (val >= 0.0f) atomicMax((int*)addr, __float_as_int(val));
    else             atomicMin((unsigned int*)addr, __float_as_uint(val));
}

__global__ void init_kernel(float* __restrict__ out) {
    int i = blockIdx.x * blockDim.x + threadIdx.x;
    if (i < BATCH * 4 * HWC) out[i] = -FLT_MAX;
    if (i < BATCH * 2)       g_D[i] = 0.0f;   // d >= 0 always
}

// Global branch: out[b,ch,p] = max_q sim[b,q,p] * seg[b,ch,q], ch=0,1.
// grid (6, 36, 8) = 1728 blocks, block 96. Thread owns 4 consecutive p.
__global__ void __launch_bounds__(96) global_kernel(
        const float* __restrict__ sim,
        const float* __restrict__ seg,
        float* __restrict__ out) {
    const int b  = blockIdx.z;
    const int q0 = blockIdx.y * GQCH;
    const int t  = threadIdx.x;
    const int p4 = blockIdx.x * 96 + t;       // float4 index 0..575

    __shared__ float2 w[GQCH];
    if (t < GQCH)
        w[t] = make_float2(seg[(b * 2 + 0) * HWC + q0 + t],
                           seg[(b * 2 + 1) * HWC + q0 + t]);
    __syncthreads();

    const float4* base = reinterpret_cast<const float4*>(
        sim + ((size_t)b * HWC + q0) * HWC) + p4;

    float4 a0 = make_float4(-FLT_MAX, -FLT_MAX, -FLT_MAX, -FLT_MAX);
    float4 a1 = a0;
#pragma unroll 8
    for (int j = 0; j < GQCH; j++) {
        float4 v  = base[(size_t)j * (HWC / 4)];
        float2 ww = w[j];
        a0.x = fmaxf(a0.x, v.x * ww.x); a0.y = fmaxf(a0.y, v.y * ww.x);
        a0.z = fmaxf(a0.z, v.z * ww.x); a0.w = fmaxf(a0.w, v.w * ww.x);
        a1.x = fmaxf(a1.x, v.x * ww.y); a1.y = fmaxf(a1.y, v.y * ww.y);
        a1.z = fmaxf(a1.z, v.z * ww.y); a1.w = fmaxf(a1.w, v.w * ww.y);
    }
    float* o0 = out + (size_t)(b * 4 + 0) * HWC + 4 * p4;
    float* o1 = out + (size_t)(b * 4 + 1) * HWC + 4 * p4;
    atomicMaxF(o0 + 0, a0.x); atomicMaxF(o0 + 1, a0.y);
    atomicMaxF(o0 + 2, a0.z); atomicMaxF(o0 + 3, a0.w);
    atomicMaxF(o1 + 0, a1.x); atomicMaxF(o1 + 1, a1.y);
    atomicMaxF(o1 + 2, a1.z); atomicMaxF(o1 + 3, a1.w);
}

// Merge two descending sorted 4-lists (v0..v3) across shuffle distance o.
#define MERGE4V(o)                                                             \
    {                                                                          \
        float b0 = __shfl_xor_sync(0xffffffffu, v0, o);                        \
        float b1 = __shfl_xor_sync(0xffffffffu, v1, o);                        \
        float b2 = __shfl_xor_sync(0xffffffffu, v2, o);                        \
        float b3 = __shfl_xor_sync(0xffffffffu, v3, o);                        \
        float c0 = fmaxf(v0, b3), c1 = fmaxf(v1, b2);                          \
        float c2 = fmaxf(v2, b1), c3 = fmaxf(v3, b0);                          \
        float tt;                                                              \
        tt = fmaxf(c0, c2); c2 = fminf(c0, c2); c0 = tt;                       \
        tt = fmaxf(c1, c3); c3 = fminf(c1, c3); c1 = tt;                       \
        tt = fmaxf(c0, c1); c1 = fminf(c0, c1); c0 = tt;                       \
        tt = fmaxf(c2, c3); c3 = fminf(c2, c3); c2 = tt;                       \
        v0 = c0; v1 = c1; v2 = c2; v3 = c3;                                    \
    }

// Local branch: one WARP per row of prev_sim; block = 4 warps = 4 rows.
// Pass A: stream row -> smem; per-lane max & min only (2 ops/elem).
// t = 4th largest of 32 lane-maxima (lower bound on true 4th-largest: any
// subset's 4th-largest <= full set's). Row min reduced exactly.
// Pass B: compact all elements >= t (expected ~10) into (val,pos) list.
// Exact cut = 4th largest of list; emit scale*val for list entries >= cut.
__global__ void __launch_bounds__(32 * LROWS) local_kernel(
        const float* __restrict__ sim,
        const float* __restrict__ seg,
        float* __restrict__ out) {
    __shared__ float s_row[LROWS][HWC];
    __shared__ float s_val[LROWS][LCAP];
    __shared__ int   s_pos[LROWS][LCAP];
    __shared__ int   s_cnt[LROWS];
    __shared__ float s_cut[LROWS];

    const int t    = threadIdx.x;
    const int lane = t & 31, w = t >> 5;
    const int row  = blockIdx.x * LROWS + w;    // b*HWC + q
    const int b    = row / HWC;
    const int q    = row - b * HWC;

    const float4* r4  = reinterpret_cast<const float4*>(sim + (size_t)row * HWC);
    float4*       sr4 = reinterpret_cast<float4*>(s_row[w]);

    if (lane == 0) s_cnt[w] = 0;

    // ---- Pass A: stream + lane max/min ----
    float lmax = -FLT_MAX, lmin = FLT_MAX;
#pragma unroll 6
    for (int j = 0; j < HWC / 128; j++) {           // 18 iters
        float4 v = r4[j * 32 + lane];
        sr4[j * 32 + lane] = v;
        lmax = fmaxf(lmax, fmaxf(fmaxf(v.x, v.y), fmaxf(v.z, v.w)));
        lmin = fminf(lmin, fminf(fminf(v.x, v.y), fminf(v.z, v.w)));
    }
    __syncwarp();

    // exact row min
    float mn = lmin;
#pragma unroll
    for (int o = 16; o; o >>= 1) mn = fminf(mn, __shfl_xor_sync(0xffffffffu, mn, o));

    // t = 4th largest of the 32 lane maxima
    float v0 = lmax, v1 = -FLT_MAX, v2 = -FLT_MAX, v3 = -FLT_MAX;
    MERGE4V(16); MERGE4V(8); MERGE4V(4); MERGE4V(2); MERGE4V(1);
    const float tb = v3;                            // lower bound on true cut

    // ---- Pass B: compact candidates >= tb ----
#pragma unroll
    for (int j = 0; j < HWC / 128; j++) {
        float4 v = sr4[j * 32 + lane];
        int pbase = j * 128 + lane * 4;
        if (v.x >= tb) { int id = atomicAdd(&s_cnt[w], 1); if (id < LCAP) { s_val[w][id] = v.x; s_pos[w][id] = pbase + 0; } }
        if (v.y >= tb) { int id = atomicAdd(&s_cnt[w], 1); if (id < LCAP) { s_val[w][id] = v.y; s_pos[w][id] = pbase + 1; } }
        if (v.z >= tb) { int id = atomicAdd(&s_cnt[w], 1); if (id < LCAP) { s_val[w][id] = v.z; s_pos[w][id] = pbase + 2; } }
        if (v.w >= tb) { int id = atomicAdd(&s_cnt[w], 1); if (id < LCAP) { s_val[w][id] = v.w; s_pos[w][id] = pbase + 3; } }
    }
    __syncwarp();

    int   cnt = s_cnt[w];
    float cut;
    if (cnt <= LCAP) {
        // exact cut = 4th largest of candidate list (>= 4 entries guaranteed:
        // the 4 top lane-max elements are all >= tb)
        v0 = v1 = v2 = v3 = -FLT_MAX;
#pragma unroll
        for (int k = 0; k < LCAP / 32; k++) {
            int id = lane + 32 * k;
            float x = (id < cnt) ? s_val[w][id] : -FLT_MAX;
            v3 = fminf(v2, fmaxf(v3, x));
            v2 = fminf(v1, fmaxf(v2, x));
            v1 = fminf(v0, fmaxf(v1, x));
            v0 = fmaxf(v0, x);
        }
        MERGE4V(16); MERGE4V(8); MERGE4V(4); MERGE4V(2); MERGE4V(1);
        cut = v3;
    } else {
        // overflow fallback (never taken for random data): exact serial cut,
        // then rebuild the list with the exact threshold.
        if (lane == 0) {
            float u0 = -FLT_MAX, u1 = -FLT_MAX, u2 = -FLT_MAX, u3 = -FLT_MAX;
            for (int i = 0; i < HWC; i++) {
                float x = s_row[w][i];
                u3 = fminf(u2, fmaxf(u3, x));
                u2 = fminf(u1, fmaxf(u2, x));
                u1 = fminf(u0, fmaxf(u1, x));
                u0 = fmaxf(u0, x);
            }
            s_cut[w] = u3;
            s_cnt[w] = 0;
        }
        __syncwarp();
        cut = s_cut[w];
#pragma unroll
        for (int j = 0; j < HWC / 128; j++) {
            float4 v = sr4[j * 32 + lane];
            int pbase = j * 128 + lane * 4;
            if (v.x >= cut) { int id = atomicAdd(&s_cnt[w], 1); if (id < LCAP) { s_val[w][id] = v.x; s_pos[w][id] = pbase + 0; } }
            if (v.y >= cut) { int id = atomicAdd(&s_cnt[w], 1); if (id < LCAP) { s_val[w][id] = v.y; s_pos[w][id] = pbase + 1; } }
            if (v.z >= cut) { int id = atomicAdd(&s_cnt[w], 1); if (id < LCAP) { s_val[w][id] = v.z; s_pos[w][id] = pbase + 2; } }
            if (v.w >= cut) { int id = atomicAdd(&s_cnt[w], 1); if (id < LCAP) { s_val[w][id] = v.w; s_pos[w][id] = pbase + 3; } }
        }
        __syncwarp();
        cnt = s_cnt[w];
    }
    if (cnt > LCAP) cnt = LCAP;

    // ---- Emission ----
    float sc0 = 0.f, sc1 = 0.f;
    if (lane == 0) {
        sc0 = seg[(b * 2 + 0) * HWC + q];
        sc1 = seg[(b * 2 + 1) * HWC + q];
    }
    sc0 = __shfl_sync(0xffffffffu, sc0, 0);
    sc1 = __shfl_sync(0xffffffffu, sc1, 0);

    float* o2 = out + (size_t)(b * 4 + 2) * HWC;
    float* o3 = out + (size_t)(b * 4 + 3) * HWC;
#pragma unroll
    for (int k = 0; k < LCAP / 32; k++) {
        int id = lane + 32 * k;
        if (id < cnt) {
            float x = s_val[w][id];
            if (x >= cut) {
                int p = s_pos[w][id];
                atomicMaxF(o2 + p, sc0 * x);
                atomicMaxF(o3 + p, sc1 * x);
            }
        }
    }
    if (lane == 0) {
        atomicMaxF(&g_D[b * 2 + 0], fmaxf(sc0 * mn, 0.0f));
        atomicMaxF(&g_D[b * 2 + 1], fmaxf(sc1 * mn, 0.0f));
    }
}

// Merge broadcast "dropped" value D into local channels (2,3).
__global__ void finalize_kernel(float* __restrict__ out) {
    int i = blockIdx.x * blockDim.x + threadIdx.x;   // over BATCH*2*HWC
    if (i >= BATCH * 2 * HWC) return;
    int b   = i / (2 * HWC);
    int rem = i - b * 2 * HWC;
    int ch  = rem / HWC;
    int p   = rem - ch * HWC;
    float D = g_D[b * 2 + ch];
    float* o = &out[(size_t)(b * 4 + 2 + ch) * HWC + p];
    *o = fmaxf(*o, D);
}

extern "C" void kernel_launch(void* const* d_in, const int* in_sizes, int n_in,
                              void* d_out, int out_size) {
    const float* init_sim = (const float*)d_in[0];
    const float* prev_sim = (const float*)d_in[1];
    const float* init_seg = (const float*)d_in[2];
    const float* prev_seg = (const float*)d_in[3];
    float* out = (float*)d_out;

    init_kernel<<<(BATCH * 4 * HWC + 255) / 256, 256>>>(out);

    dim3 g(HWC / 4 / 96, HWC / GQCH, BATCH);   // (6, 36, 8) = 1728 blocks
    global_kernel<<<g, 96>>>(init_sim, init_seg, out);

    local_kernel<<<BATCH * HWC / LROWS, 32 * LROWS>>>(prev_sim, prev_seg, out);

    finalize_kernel<<<(BATCH * 2 * HWC + 255) / 256, 256>>>(out);
}

// round 5
// speedup vs baseline: 1.5191x; 1.1072x over previous
#include <cuda_runtime.h>
#include <float.h>

#define HWC   2304      // H*W = 48*48
#define BATCH 8
#define GQCH  64        // q-chunk in global kernel
#define LROWS 4         // rows per local block (one warp each)
#define LCAP  128       // candidate-list capacity per row

// per-(batch, channel) max of "dropped" value d = max(scale*rowmin, 0) >= 0
__device__ float g_D[BATCH * 2];

// Float atomic max via signed-int max / unsigned-int min (IEEE order trick).
// General form (used for global branch, values may be negative).
__device__ __forceinline__ void atomicMaxF(float* addr, float val) {
    if (val >= 0.0f) atomicMax((int*)addr, __float_as_int(val));
    else             atomicMin((unsigned int*)addr, __float_as_uint(val));
}
// Positive-domain form: valid when *addr and val are both >= 0.
__device__ __forceinline__ void atomicMaxFPos(float* addr, float val) {
    atomicMax((int*)addr, __float_as_int(val));
}

// ch0/1 <- -FLT_MAX (global branch, values may be negative);
// ch2/3 <- 0 (local branch outputs are provably >= 0); g_D <- 0.
__global__ void init_kernel(float* __restrict__ out) {
    int i = blockIdx.x * blockDim.x + threadIdx.x;       // float4 index
    if (i < BATCH * 4 * HWC / 4) {
        int ch = (i * 4 / HWC) & 3;                      // channel 0..3
        float f = (ch < 2) ? -FLT_MAX : 0.0f;
        reinterpret_cast<float4*>(out)[i] = make_float4(f, f, f, f);
    }
    if (i < BATCH * 2) g_D[i] = 0.0f;
}

// Global branch: out[b,ch,p] = max_q sim[b,q,p] * seg[b,ch,q], ch=0,1.
// grid (6, 36, 8) = 1728 blocks, block 96. Thread owns 4 consecutive p.
// Runs LAST: its y==0 blocks also merge g_D into local channels 2,3.
__global__ void __launch_bounds__(96) global_kernel(
        const float* __restrict__ sim,
        const float* __restrict__ seg,
        float* __restrict__ out) {
    const int b  = blockIdx.z;
    const int q0 = blockIdx.y * GQCH;
    const int t  = threadIdx.x;
    const int p4 = blockIdx.x * 96 + t;       // float4 index 0..575

    __shared__ float2 w[GQCH];
    if (t < GQCH)
        w[t] = make_float2(seg[(b * 2 + 0) * HWC + q0 + t],
                           seg[(b * 2 + 1) * HWC + q0 + t]);
    __syncthreads();

    const float4* base = reinterpret_cast<const float4*>(
        sim + ((size_t)b * HWC + q0) * HWC) + p4;

    float4 a0 = make_float4(-FLT_MAX, -FLT_MAX, -FLT_MAX, -FLT_MAX);
    float4 a1 = a0;
#pragma unroll 8
    for (int j = 0; j < GQCH; j++) {
        float4 v  = base[(size_t)j * (HWC / 4)];
        float2 ww = w[j];
        a0.x = fmaxf(a0.x, v.x * ww.x); a0.y = fmaxf(a0.y, v.y * ww.x);
        a0.z = fmaxf(a0.z, v.z * ww.x); a0.w = fmaxf(a0.w, v.w * ww.x);
        a1.x = fmaxf(a1.x, v.x * ww.y); a1.y = fmaxf(a1.y, v.y * ww.y);
        a1.z = fmaxf(a1.z, v.z * ww.y); a1.w = fmaxf(a1.w, v.w * ww.y);
    }
    float* o0 = out + (size_t)(b * 4 + 0) * HWC + 4 * p4;
    float* o1 = out + (size_t)(b * 4 + 1) * HWC + 4 * p4;
    atomicMaxF(o0 + 0, a0.x); atomicMaxF(o0 + 1, a0.y);
    atomicMaxF(o0 + 2, a0.z); atomicMaxF(o0 + 3, a0.w);
    atomicMaxF(o1 + 0, a1.x); atomicMaxF(o1 + 1, a1.y);
    atomicMaxF(o1 + 2, a1.z); atomicMaxF(o1 + 3, a1.w);

    // Finalize tail: merge broadcast D into channels 2,3 for this p-tile.
    // local_kernel completed before this launch (stream order), and only
    // this block touches these addresses within this kernel.
    if (blockIdx.y == 0) {
        const float D0 = g_D[b * 2 + 0];
        const float D1 = g_D[b * 2 + 1];
        float4* o2 = reinterpret_cast<float4*>(out + (size_t)(b * 4 + 2) * HWC) + p4;
        float4* o3 = reinterpret_cast<float4*>(out + (size_t)(b * 4 + 3) * HWC) + p4;
        float4 v2 = *o2, v3 = *o3;
        v2.x = fmaxf(v2.x, D0); v2.y = fmaxf(v2.y, D0);
        v2.z = fmaxf(v2.z, D0); v2.w = fmaxf(v2.w, D0);
        v3.x = fmaxf(v3.x, D1); v3.y = fmaxf(v3.y, D1);
        v3.z = fmaxf(v3.z, D1); v3.w = fmaxf(v3.w, D1);
        *o2 = v2; *o3 = v3;
    }
}

// Merge two descending sorted 4-lists (v0..v3) across shuffle distance o.
#define MERGE4V(o)                                                             \
    {                                                                          \
        float b0 = __shfl_xor_sync(0xffffffffu, v0, o);                        \
        float b1 = __shfl_xor_sync(0xffffffffu, v1, o);                        \
        float b2 = __shfl_xor_sync(0xffffffffu, v2, o);                        \
        float b3 = __shfl_xor_sync(0xffffffffu, v3, o);                        \
        float c0 = fmaxf(v0, b3), c1 = fmaxf(v1, b2);                          \
        float c2 = fmaxf(v2, b1), c3 = fmaxf(v3, b0);                          \
        float tt;                                                              \
        tt = fmaxf(c0, c2); c2 = fminf(c0, c2); c0 = tt;                       \
        tt = fmaxf(c1, c3); c3 = fminf(c1, c3); c1 = tt;                       \
        tt = fmaxf(c0, c1); c1 = fminf(c0, c1); c0 = tt;                       \
        tt = fmaxf(c2, c3); c3 = fminf(c2, c3); c2 = tt;                       \
        v0 = c0; v1 = c1; v2 = c2; v3 = c3;                                    \
    }

// Local branch: one WARP per row of prev_sim; block = 4 warps = 4 rows.
// Pass A: stream row -> smem; per-lane max & min only (2 ops/elem).
// tb = 4th largest of 32 lane-maxima (lower bound on true 4th-largest).
// Pass B: compact all elements >= tb (expected ~10) into (val,pos) list.
// Exact cut = 4th largest of list; emit scale*val for entries >= cut.
// All emissions land in the non-negative domain (ch2/3 init = 0).
__global__ void __launch_bounds__(32 * LROWS) local_kernel(
        const float* __restrict__ sim,
        const float* __restrict__ seg,
        float* __restrict__ out) {
    __shared__ float s_row[LROWS][HWC];
    __shared__ float s_val[LROWS][LCAP];
    __shared__ int   s_pos[LROWS][LCAP];
    __shared__ int   s_cnt[LROWS];
    __shared__ float s_cut[LROWS];

    const int t    = threadIdx.x;
    const int lane = t & 31, w = t >> 5;
    const int row  = blockIdx.x * LROWS + w;    // b*HWC + q
    const int b    = row / HWC;
    const int q    = row - b * HWC;

    const float4* r4  = reinterpret_cast<const float4*>(sim + (size_t)row * HWC);
    float4*       sr4 = reinterpret_cast<float4*>(s_row[w]);

    if (lane == 0) s_cnt[w] = 0;

    // ---- Pass A: stream + lane max/min ----
    float lmax = -FLT_MAX, lmin = FLT_MAX;
#pragma unroll 9
    for (int j = 0; j < HWC / 128; j++) {           // 18 iters
        float4 v = r4[j * 32 + lane];
        sr4[j * 32 + lane] = v;
        lmax = fmaxf(lmax, fmaxf(fmaxf(v.x, v.y), fmaxf(v.z, v.w)));
        lmin = fminf(lmin, fminf(fminf(v.x, v.y), fminf(v.z, v.w)));
    }
    __syncwarp();

    // exact row min
    float mn = lmin;
#pragma unroll
    for (int o = 16; o; o >>= 1) mn = fminf(mn, __shfl_xor_sync(0xffffffffu, mn, o));

    // tb = 4th largest of the 32 lane maxima
    float v0 = lmax, v1 = -FLT_MAX, v2 = -FLT_MAX, v3 = -FLT_MAX;
    MERGE4V(16); MERGE4V(8); MERGE4V(4); MERGE4V(2); MERGE4V(1);
    const float tb = v3;                            // lower bound on true cut

    // ---- Pass B: compact candidates >= tb ----
#pragma unroll
    for (int j = 0; j < HWC / 128; j++) {
        float4 v = sr4[j * 32 + lane];
        int pbase = j * 128 + lane * 4;
        if (v.x >= tb) { int id = atomicAdd(&s_cnt[w], 1); if (id < LCAP) { s_val[w][id] = v.x; s_pos[w][id] = pbase + 0; } }
        if (v.y >= tb) { int id = atomicAdd(&s_cnt[w], 1); if (id < LCAP) { s_val[w][id] = v.y; s_pos[w][id] = pbase + 1; } }
        if (v.z >= tb) { int id = atomicAdd(&s_cnt[w], 1); if (id < LCAP) { s_val[w][id] = v.z; s_pos[w][id] = pbase + 2; } }
        if (v.w >= tb) { int id = atomicAdd(&s_cnt[w], 1); if (id < LCAP) { s_val[w][id] = v.w; s_pos[w][id] = pbase + 3; } }
    }
    __syncwarp();

    int   cnt = s_cnt[w];
    float cut;
    if (cnt <= LCAP) {
        // exact cut = 4th largest of candidate list (>= 4 entries guaranteed)
        v0 = v1 = v2 = v3 = -FLT_MAX;
#pragma unroll
        for (int k = 0; k < LCAP / 32; k++) {
            int id = lane + 32 * k;
            float x = (id < cnt) ? s_val[w][id] : -FLT_MAX;
            v3 = fminf(v2, fmaxf(v3, x));
            v2 = fminf(v1, fmaxf(v2, x));
            v1 = fminf(v0, fmaxf(v1, x));
            v0 = fmaxf(v0, x);
        }
        MERGE4V(16); MERGE4V(8); MERGE4V(4); MERGE4V(2); MERGE4V(1);
        cut = v3;
    } else {
        // overflow fallback (never taken for random data): exact serial cut,
        // then rebuild the list with the exact threshold.
        if (lane == 0) {
            float u0 = -FLT_MAX, u1 = -FLT_MAX, u2 = -FLT_MAX, u3 = -FLT_MAX;
            for (int i = 0; i < HWC; i++) {
                float x = s_row[w][i];
                u3 = fminf(u2, fmaxf(u3, x));
                u2 = fminf(u1, fmaxf(u2, x));
                u1 = fminf(u0, fmaxf(u1, x));
                u0 = fmaxf(u0, x);
            }
            s_cut[w] = u3;
            s_cnt[w] = 0;
        }
        __syncwarp();
        cut = s_cut[w];
#pragma unroll
        for (int j = 0; j < HWC / 128; j++) {
            float4 v = sr4[j * 32 + lane];
            int pbase = j * 128 + lane * 4;
            if (v.x >= cut) { int id = atomicAdd(&s_cnt[w], 1); if (id < LCAP) { s_val[w][id] = v.x; s_pos[w][id] = pbase + 0; } }
            if (v.y >= cut) { int id = atomicAdd(&s_cnt[w], 1); if (id < LCAP) { s_val[w][id] = v.y; s_pos[w][id] = pbase + 1; } }
            if (v.z >= cut) { int id = atomicAdd(&s_cnt[w], 1); if (id < LCAP) { s_val[w][id] = v.z; s_pos[w][id] = pbase + 2; } }
            if (v.w >= cut) { int id = atomicAdd(&s_cnt[w], 1); if (id < LCAP) { s_val[w][id] = v.w; s_pos[w][id] = pbase + 3; } }
        }
        __syncwarp();
        cnt = s_cnt[w];
    }
    if (cnt > LCAP) cnt = LCAP;

    // ---- Emission (positive domain: skip <= 0, they can never beat D) ----
    float sc0 = 0.f, sc1 = 0.f;
    if (lane == 0) {
        sc0 = seg[(b * 2 + 0) * HWC + q];
        sc1 = seg[(b * 2 + 1) * HWC + q];
    }
    sc0 = __shfl_sync(0xffffffffu, sc0, 0);
    sc1 = __shfl_sync(0xffffffffu, sc1, 0);

    float* o2 = out + (size_t)(b * 4 + 2) * HWC;
    float* o3 = out + (size_t)(b * 4 + 3) * HWC;
#pragma unroll
    for (int k = 0; k < LCAP / 32; k++) {
        int id = lane + 32 * k;
        if (id < cnt) {
            float x = s_val[w][id];
            if (x >= cut) {
                int p = s_pos[w][id];
                float e0 = sc0 * x, e1 = sc1 * x;
                if (e0 > 0.0f) atomicMaxFPos(o2 + p, e0);
                if (e1 > 0.0f) atomicMaxFPos(o3 + p, e1);
            }
        }
    }
    if (lane == 0) {
        float d0 = fmaxf(sc0 * mn, 0.0f);
        float d1 = fmaxf(sc1 * mn, 0.0f);
        if (d0 > 0.0f) atomicMaxFPos(&g_D[b * 2 + 0], d0);
        if (d1 > 0.0f) atomicMaxFPos(&g_D[b * 2 + 1], d1);
    }
}

extern "C" void kernel_launch(void* const* d_in, const int* in_sizes, int n_in,
                              void* d_out, int out_size) {
    const float* init_sim = (const float*)d_in[0];
    const float* prev_sim = (const float*)d_in[1];
    const float* init_seg = (const float*)d_in[2];
    const float* prev_seg = (const float*)d_in[3];
    float* out = (float*)d_out;

    init_kernel<<<(BATCH * 4 * HWC / 4 + 255) / 256, 256>>>(out);

    local_kernel<<<BATCH * HWC / LROWS, 32 * LROWS>>>(prev_sim, prev_seg, out);

    dim3 g(HWC / 4 / 96, HWC / GQCH, BATCH);   // (6, 36, 8) = 1728 blocks
    global_kernel<<<g, 96>>>(init_sim, init_seg, out);  // + D-merge tail
}